// round 10
// baseline (speedup 1.0000x reference)
#include <cuda_runtime.h>
#include <cuda_bf16.h>
#include <cuda_fp16.h>
#include <cstdint>

// B*W = 2048 independent problems.
//   query  [S=128, D=64]  fp32 (shared)   keys/values [BW, T=256, D=64] fp32
//   out    [BW, S=128, D=64] fp32
#define S_DIM 128
#define D_DIM 64
#define T_DIM 256
#define CHUNK 64
#define NCHUNK (T_DIM / CHUNK)
#define THREADS 256

// smem (bytes): Q hi/lo bf16 + K hi/lo bf16 + V fp16   (no staging tier)
#define SM_QH   0                        // [128][64] bf16 = 16KB
#define SM_QL   16384
#define SM_KH   32768                    // [64][64] bf16 = 8KB
#define SM_KL   40960
#define SM_VF   49152                    // [64][64] fp16 = 8KB
#define SMEM_BYTES 57344                 // 56KB -> 2 CTAs/SM (regs are the cap)

#define L2E 1.4426950408889634f

__device__ __forceinline__ uint32_t smem_u32(const void* p) {
    uint32_t a;
    asm("{ .reg .u64 t; cvta.to.shared.u64 t, %1; cvt.u32.u64 %0, t; }" : "=r"(a) : "l"(p));
    return a;
}
__device__ __forceinline__ uint32_t swz(uint32_t b) { return b ^ ((b >> 3) & 0x70); }
__device__ __forceinline__ void prefetch_l2(const void* p) {
    asm volatile("prefetch.global.L2 [%0];" :: "l"(p));
}

// ---- cheap split: hi = truncated bf16 (packed via PRMT), lo = rn(residual) ----
__device__ __forceinline__ void splitpack_fast(float x, float y, uint32_t& hp, uint32_t& lp) {
    uint32_t xi = __float_as_uint(x), yi = __float_as_uint(y);
    hp = __byte_perm(xi, yi, 0x7632);                       // {y_hi16, x_hi16}
    float xh = __uint_as_float(xi & 0xFFFF0000u);
    float yh = __uint_as_float(yi & 0xFFFF0000u);
    __nv_bfloat162 p = __floats2bfloat162_rn(x - xh, y - yh);
    lp = *(uint32_t*)&p;
}
__device__ __forceinline__ uint32_t packh2(float a, float b) {
    __half2 p = __floats2half2_rn(a, b);
    return *(uint32_t*)&p;
}
// packed 2^((a - m)·log2e) in fp16x2; mlog = -m*L2E precomputed
__device__ __forceinline__ uint32_t ex2h2(float a, float b, float mlog) {
    float xa = fmaf(a, L2E, mlog);
    float xb = fmaf(b, L2E, mlog);
    uint32_t r = packh2(xa, xb), o;
    asm("ex2.approx.f16x2 %0, %1;" : "=r"(o) : "r"(r));
    return o;
}

#define LDSM_X4(R0,R1,R2,R3,A) \
    asm volatile("ldmatrix.sync.aligned.m8n8.x4.shared.b16 {%0,%1,%2,%3}, [%4];" \
        : "=r"(R0),"=r"(R1),"=r"(R2),"=r"(R3) : "r"(A))
#define LDSM_X4T(R0,R1,R2,R3,A) \
    asm volatile("ldmatrix.sync.aligned.m8n8.x4.trans.shared.b16 {%0,%1,%2,%3}, [%4];" \
        : "=r"(R0),"=r"(R1),"=r"(R2),"=r"(R3) : "r"(A))

__device__ __forceinline__ void mma_bf16(float c[4], const uint32_t a[4], const uint32_t b[2]) {
    asm volatile("mma.sync.aligned.m16n8k16.row.col.f32.bf16.bf16.f32 "
        "{%0,%1,%2,%3}, {%4,%5,%6,%7}, {%8,%9}, {%0,%1,%2,%3};"
        : "+f"(c[0]), "+f"(c[1]), "+f"(c[2]), "+f"(c[3])
        : "r"(a[0]), "r"(a[1]), "r"(a[2]), "r"(a[3]), "r"(b[0]), "r"(b[1]));
}
__device__ __forceinline__ void mma_f16(float c[4], const uint32_t a[4], const uint32_t b[2]) {
    asm volatile("mma.sync.aligned.m16n8k16.row.col.f32.f16.f16.f32 "
        "{%0,%1,%2,%3}, {%4,%5,%6,%7}, {%8,%9}, {%0,%1,%2,%3};"
        : "+f"(c[0]), "+f"(c[1]), "+f"(c[2]), "+f"(c[3])
        : "r"(a[0]), "r"(a[1]), "r"(a[2]), "r"(a[3]), "r"(b[0]), "r"(b[1]));
}

__global__ void __launch_bounds__(THREADS, 2)
attn_flash7_kernel(const float* __restrict__ q,
                   const float* __restrict__ keys,
                   const float* __restrict__ values,
                   float* __restrict__ out)
{
    extern __shared__ char smem[];
    const uint32_t sb = smem_u32(smem);
    const int tid = threadIdx.x;
    const int w   = tid >> 5;
    const int l   = tid & 31;
    const int bw  = blockIdx.x;
    const int s0  = w * 16;

    const char* kg = (const char*)(keys   + (size_t)bw * T_DIM * D_DIM);
    const char* vg = (const char*)(values + (size_t)bw * T_DIM * D_DIM);

    // ---- convert Q -> smem bf16 hi/lo (16B stores) ----
    {
        const float4* q4 = (const float4*)q;
        #pragma unroll
        for (int i = tid; i < S_DIM * 8; i += THREADS) {
            int s = i >> 3, d8 = i & 7;
            uint32_t off = swz((uint32_t)(s * 128 + d8 * 16));
            float4 a = q4[s * 16 + d8 * 2];
            float4 b = q4[s * 16 + d8 * 2 + 1];
            uint32_t h0,l0,h1,l1,h2,l2,h3,l3;
            splitpack_fast(a.x, a.y, h0, l0);
            splitpack_fast(a.z, a.w, h1, l1);
            splitpack_fast(b.x, b.y, h2, l2);
            splitpack_fast(b.z, b.w, h3, l3);
            *(uint4*)(smem + SM_QH + off) = make_uint4(h0, h1, h2, h3);
            *(uint4*)(smem + SM_QL + off) = make_uint4(l0, l1, l2, l3);
        }
    }

    // ldmatrix lane patterns
    const int a_row  = l & 15;
    const int a_kh   = l >> 4;
    const int b_i    = l >> 3;
    const int b_row  = l & 7;
    const int b_nh   = (b_i >> 1) * 8;
    const int b_kh   = (b_i & 1) * 16;
    const int b_toff = (b_i & 1) * 8 + (l & 7);
    const int b_ch   = (b_i >> 1) * 16;

    float Oacc[8][4];
    #pragma unroll
    for (int nt = 0; nt < 8; ++nt)
        #pragma unroll
        for (int e = 0; e < 4; ++e) Oacc[nt][e] = 0.0f;
    float c_rs[4] = {0.0f, 0.0f, 0.0f, 0.0f};   // row sums via ones-MMA
    const uint32_t onesb[2] = {0x3C003C00u, 0x3C003C00u};
    float m1 = -3.0e38f, m2 = -3.0e38f;          // running row maxima

    for (int chunk = 0; chunk < NCHUNK; ++chunk) {
        const int base = chunk * (CHUNK * D_DIM * 4);
        __syncthreads();           // prev GEMM2 done: K/V tiles reusable

        // ---- convert global fp32 -> K bf16 hi/lo, V fp16 (LDG.128 -> STS.128) ----
        {
            const float4* kc = (const float4*)(kg + base);
            const float4* vc = (const float4*)(vg + base);
            #pragma unroll
            for (int i = tid; i < CHUNK * 8; i += THREADS) {
                int t = i >> 3, d8 = i & 7;
                uint32_t off = swz((uint32_t)(t * 128 + d8 * 16));
                float4 a = kc[t * 16 + d8 * 2];
                float4 b = kc[t * 16 + d8 * 2 + 1];
                float4 va = vc[t * 16 + d8 * 2];
                float4 vb = vc[t * 16 + d8 * 2 + 1];
                uint32_t h0,l0,h1,l1,h2,l2,h3,l3;
                splitpack_fast(a.x, a.y, h0, l0);
                splitpack_fast(a.z, a.w, h1, l1);
                splitpack_fast(b.x, b.y, h2, l2);
                splitpack_fast(b.z, b.w, h3, l3);
                *(uint4*)(smem + SM_KH + off) = make_uint4(h0, h1, h2, h3);
                *(uint4*)(smem + SM_KL + off) = make_uint4(l0, l1, l2, l3);
                *(uint4*)(smem + SM_VF + off) = make_uint4(packh2(va.x, va.y), packh2(va.z, va.w),
                                                           packh2(vb.x, vb.y), packh2(vb.z, vb.w));
            }
        }
        __syncthreads();           // tiles visible

        // ---- L2-prefetch next chunk (no registers, overlaps GEMMs) ----
        if (chunk < NCHUNK - 1) {
            const int nbase = base + CHUNK * D_DIM * 4;
            if (tid < 128) prefetch_l2(kg + nbase + tid * 128);
            else           prefetch_l2(vg + nbase + (tid - 128) * 128);
        }

        // ---- GEMM1: S = Q @ K^T  [16 x 64] per warp, split-3 bf16 ----
        float acc[8][4];
        #pragma unroll
        for (int nt = 0; nt < 8; ++nt)
            #pragma unroll
            for (int e = 0; e < 4; ++e) acc[nt][e] = 0.0f;

        #pragma unroll
        for (int k16 = 0; k16 < 4; ++k16) {
            uint32_t Ah[4], Al[4];
            {
                uint32_t off = swz((uint32_t)((s0 + a_row) * 128 + k16 * 32 + a_kh * 16));
                LDSM_X4(Ah[0], Ah[1], Ah[2], Ah[3], sb + SM_QH + off);
                LDSM_X4(Al[0], Al[1], Al[2], Al[3], sb + SM_QL + off);
            }
            #pragma unroll
            for (int ntp = 0; ntp < 4; ++ntp) {
                uint32_t Bh[2][2], Bl[2][2];
                uint32_t off = swz((uint32_t)((ntp * 16 + b_nh + b_row) * 128 + k16 * 32 + b_kh));
                LDSM_X4(Bh[0][0], Bh[0][1], Bh[1][0], Bh[1][1], sb + SM_KH + off);
                LDSM_X4(Bl[0][0], Bl[0][1], Bl[1][0], Bl[1][1], sb + SM_KL + off);
                #pragma unroll
                for (int j = 0; j < 2; ++j) {
                    int nt = 2 * ntp + j;
                    mma_bf16(acc[nt], Ah, Bh[j]);
                    mma_bf16(acc[nt], Ah, Bl[j]);
                    mma_bf16(acc[nt], Al, Bh[j]);
                }
            }
        }

        // ---- mask + online max ----
        #pragma unroll
        for (int nt = 0; nt < 8; ++nt)
            #pragma unroll
            for (int e = 0; e < 4; ++e) {
                float v = acc[nt][e];
                acc[nt][e] = (v == 0.0f) ? -100000.0f : v;
            }
        float cm1 = -3.0e38f, cm2 = -3.0e38f;
        #pragma unroll
        for (int nt = 0; nt < 8; ++nt) {
            cm1 = fmaxf(cm1, fmaxf(acc[nt][0], acc[nt][1]));
            cm2 = fmaxf(cm2, fmaxf(acc[nt][2], acc[nt][3]));
        }
        cm1 = fmaxf(cm1, __shfl_xor_sync(0xFFFFFFFFu, cm1, 1));
        cm1 = fmaxf(cm1, __shfl_xor_sync(0xFFFFFFFFu, cm1, 2));
        cm2 = fmaxf(cm2, __shfl_xor_sync(0xFFFFFFFFu, cm2, 1));
        cm2 = fmaxf(cm2, __shfl_xor_sync(0xFFFFFFFFu, cm2, 2));

        // conditional rescale: skip when no lane's row max changed
        bool nochg = (cm1 <= m1) & (cm2 <= m2);
        if (!__all_sync(0xFFFFFFFFu, nochg)) {
            float nm1 = fmaxf(m1, cm1), nm2 = fmaxf(m2, cm2);
            float sc1 = __expf(m1 - nm1), sc2 = __expf(m2 - nm2);
            m1 = nm1; m2 = nm2;
            c_rs[0] *= sc1; c_rs[1] *= sc1;
            c_rs[2] *= sc2; c_rs[3] *= sc2;
            #pragma unroll
            for (int nt = 0; nt < 8; ++nt) {
                Oacc[nt][0] *= sc1; Oacc[nt][1] *= sc1;
                Oacc[nt][2] *= sc2; Oacc[nt][3] *= sc2;
            }
        }

        // ---- exp directly into packed fp16 P fragments ----
        const float mlog1 = -m1 * L2E, mlog2 = -m2 * L2E;
        uint32_t Pf[4][4];
        #pragma unroll
        for (int nt = 0; nt < 8; ++nt) {
            int kc = nt >> 1, j = nt & 1;
            Pf[kc][2 * j]     = ex2h2(acc[nt][0], acc[nt][1], mlog1);
            Pf[kc][2 * j + 1] = ex2h2(acc[nt][2], acc[nt][3], mlog2);
        }
        // row sums: rs += P @ ones  (consistent with GEMM2's quantized P)
        #pragma unroll
        for (int kc = 0; kc < 4; ++kc) mma_f16(c_rs, Pf[kc], onesb);

        // ---- GEMM2: O += P @ V  [16 x 64] per warp, single fp16 ----
        #pragma unroll
        for (int k16 = 0; k16 < 4; ++k16) {
            #pragma unroll
            for (int ntp = 0; ntp < 4; ++ntp) {
                uint32_t Vf[2][2];
                uint32_t off = swz((uint32_t)((k16 * 16 + b_toff) * 128 + ntp * 32 + b_ch));
                LDSM_X4T(Vf[0][0], Vf[0][1], Vf[1][0], Vf[1][1], sb + SM_VF + off);
                mma_f16(Oacc[2 * ntp],     Pf[k16], Vf[0]);
                mma_f16(Oacc[2 * ntp + 1], Pf[k16], Vf[1]);
            }
        }
    }

    // ---- epilogue: normalize by ones-MMA row sums, store ----
    float inv1 = 1.0f / c_rs[0];
    float inv2 = 1.0f / c_rs[2];

    float* ob = out + (size_t)bw * (S_DIM * D_DIM);
    const int r1 = s0 + (l >> 2), r2 = r1 + 8;
    const int ec = (l & 3) * 2;
    #pragma unroll
    for (int nt = 0; nt < 8; ++nt) {
        int c = nt * 8 + ec;
        *(float2*)(ob + r1 * 64 + c) = make_float2(Oacc[nt][0] * inv1, Oacc[nt][1] * inv1);
        *(float2*)(ob + r2 * 64 + c) = make_float2(Oacc[nt][2] * inv2, Oacc[nt][3] * inv2);
    }
}

extern "C" void kernel_launch(void* const* d_in, const int* in_sizes, int n_in,
                              void* d_out, int out_size)
{
    const float* q    = (const float*)d_in[0];
    const float* keys = (const float*)d_in[1];
    const float* vals = (const float*)d_in[2];
    float* out = (float*)d_out;

    const int BW = in_sizes[1] / (T_DIM * D_DIM);   // 2048

    cudaFuncSetAttribute(attn_flash7_kernel,
                         cudaFuncAttributeMaxDynamicSharedMemorySize, SMEM_BYTES);
    attn_flash7_kernel<<<BW, THREADS, SMEM_BYTES>>>(q, keys, vals, out);
}

// round 11
// speedup vs baseline: 1.0021x; 1.0021x over previous
#include <cuda_runtime.h>
#include <cuda_bf16.h>
#include <cuda_fp16.h>
#include <cstdint>

// B*W = 2048 independent problems.
//   query  [S=128, D=64]  fp32 (shared)   keys/values [BW, T=256, D=64] fp32
//   out    [BW, S=128, D=64] fp32
#define S_DIM 128
#define D_DIM 64
#define T_DIM 256
#define CHUNK 64
#define NCHUNK (T_DIM / CHUNK)
#define THREADS 256

// smem (bytes): Q hi/lo bf16 + K hi/lo bf16 + V fp16   (no staging tier)
#define SM_QH   0                        // [128][64] bf16 = 16KB
#define SM_QL   16384
#define SM_KH   32768                    // [64][64] bf16 = 8KB
#define SM_KL   40960
#define SM_VF   49152                    // [64][64] fp16 = 8KB
#define SMEM_BYTES 57344                 // 56KB -> 2 CTAs/SM (regs are the cap)

#define L2E 1.4426950408889634f

__device__ __forceinline__ uint32_t smem_u32(const void* p) {
    uint32_t a;
    asm("{ .reg .u64 t; cvta.to.shared.u64 t, %1; cvt.u32.u64 %0, t; }" : "=r"(a) : "l"(p));
    return a;
}
__device__ __forceinline__ uint32_t swz(uint32_t b) { return b ^ ((b >> 3) & 0x70); }
__device__ __forceinline__ void prefetch_l2(const void* p) {
    asm volatile("prefetch.global.L2 [%0];" :: "l"(p));
}

// ---- cheap split: hi = truncated bf16 (packed via PRMT), lo = rn(residual) ----
__device__ __forceinline__ void splitpack_fast(float x, float y, uint32_t& hp, uint32_t& lp) {
    uint32_t xi = __float_as_uint(x), yi = __float_as_uint(y);
    hp = __byte_perm(xi, yi, 0x7632);                       // {y_hi16, x_hi16}
    float xh = __uint_as_float(xi & 0xFFFF0000u);
    float yh = __uint_as_float(yi & 0xFFFF0000u);
    __nv_bfloat162 p = __floats2bfloat162_rn(x - xh, y - yh);
    lp = *(uint32_t*)&p;
}
__device__ __forceinline__ uint32_t packh2(float a, float b) {
    __half2 p = __floats2half2_rn(a, b);
    return *(uint32_t*)&p;
}
// packed 2^((a - m)·log2e) in fp16x2; mlog = -m*L2E precomputed
__device__ __forceinline__ uint32_t ex2h2(float a, float b, float mlog) {
    float xa = fmaf(a, L2E, mlog);
    float xb = fmaf(b, L2E, mlog);
    uint32_t r = packh2(xa, xb), o;
    asm("ex2.approx.f16x2 %0, %1;" : "=r"(o) : "r"(r));
    return o;
}

#define LDSM_X4(R0,R1,R2,R3,A) \
    asm volatile("ldmatrix.sync.aligned.m8n8.x4.shared.b16 {%0,%1,%2,%3}, [%4];" \
        : "=r"(R0),"=r"(R1),"=r"(R2),"=r"(R3) : "r"(A))
#define LDSM_X4T(R0,R1,R2,R3,A) \
    asm volatile("ldmatrix.sync.aligned.m8n8.x4.trans.shared.b16 {%0,%1,%2,%3}, [%4];" \
        : "=r"(R0),"=r"(R1),"=r"(R2),"=r"(R3) : "r"(A))

__device__ __forceinline__ void mma_bf16(float c[4], const uint32_t a[4], const uint32_t b[2]) {
    asm volatile("mma.sync.aligned.m16n8k16.row.col.f32.bf16.bf16.f32 "
        "{%0,%1,%2,%3}, {%4,%5,%6,%7}, {%8,%9}, {%0,%1,%2,%3};"
        : "+f"(c[0]), "+f"(c[1]), "+f"(c[2]), "+f"(c[3])
        : "r"(a[0]), "r"(a[1]), "r"(a[2]), "r"(a[3]), "r"(b[0]), "r"(b[1]));
}
__device__ __forceinline__ void mma_f16(float c[4], const uint32_t a[4], const uint32_t b[2]) {
    asm volatile("mma.sync.aligned.m16n8k16.row.col.f32.f16.f16.f32 "
        "{%0,%1,%2,%3}, {%4,%5,%6,%7}, {%8,%9}, {%0,%1,%2,%3};"
        : "+f"(c[0]), "+f"(c[1]), "+f"(c[2]), "+f"(c[3])
        : "r"(a[0]), "r"(a[1]), "r"(a[2]), "r"(a[3]), "r"(b[0]), "r"(b[1]));
}

__global__ void __launch_bounds__(THREADS, 2)
attn_flash7_kernel(const float* __restrict__ q,
                   const float* __restrict__ keys,
                   const float* __restrict__ values,
                   float* __restrict__ out)
{
    extern __shared__ char smem[];
    const uint32_t sb = smem_u32(smem);
    const int tid = threadIdx.x;
    const int w   = tid >> 5;
    const int l   = tid & 31;
    const int bw  = blockIdx.x;
    const int s0  = w * 16;

    const char* kg = (const char*)(keys   + (size_t)bw * T_DIM * D_DIM);
    const char* vg = (const char*)(values + (size_t)bw * T_DIM * D_DIM);

    // ---- convert Q -> smem bf16 hi/lo (16B stores) ----
    {
        const float4* q4 = (const float4*)q;
        #pragma unroll
        for (int i = tid; i < S_DIM * 8; i += THREADS) {
            int s = i >> 3, d8 = i & 7;
            uint32_t off = swz((uint32_t)(s * 128 + d8 * 16));
            float4 a = q4[s * 16 + d8 * 2];
            float4 b = q4[s * 16 + d8 * 2 + 1];
            uint32_t h0,l0,h1,l1,h2,l2,h3,l3;
            splitpack_fast(a.x, a.y, h0, l0);
            splitpack_fast(a.z, a.w, h1, l1);
            splitpack_fast(b.x, b.y, h2, l2);
            splitpack_fast(b.z, b.w, h3, l3);
            *(uint4*)(smem + SM_QH + off) = make_uint4(h0, h1, h2, h3);
            *(uint4*)(smem + SM_QL + off) = make_uint4(l0, l1, l2, l3);
        }
    }

    // ldmatrix lane patterns
    const int a_row  = l & 15;
    const int a_kh   = l >> 4;
    const int b_i    = l >> 3;
    const int b_row  = l & 7;
    const int b_nh   = (b_i >> 1) * 8;
    const int b_kh   = (b_i & 1) * 16;
    const int b_toff = (b_i & 1) * 8 + (l & 7);
    const int b_ch   = (b_i >> 1) * 16;

    float Oacc[8][4];
    #pragma unroll
    for (int nt = 0; nt < 8; ++nt)
        #pragma unroll
        for (int e = 0; e < 4; ++e) Oacc[nt][e] = 0.0f;
    float c_rs[4] = {0.0f, 0.0f, 0.0f, 0.0f};   // row sums via ones-MMA
    const uint32_t onesb[2] = {0x3C003C00u, 0x3C003C00u};
    float m1 = -3.0e38f, m2 = -3.0e38f;          // running row maxima

    for (int chunk = 0; chunk < NCHUNK; ++chunk) {
        const int base = chunk * (CHUNK * D_DIM * 4);
        __syncthreads();           // prev GEMM2 done: K/V tiles reusable

        // ---- convert global fp32 -> K bf16 hi/lo, V fp16 (LDG.128 -> STS.128) ----
        {
            const float4* kc = (const float4*)(kg + base);
            const float4* vc = (const float4*)(vg + base);
            #pragma unroll
            for (int i = tid; i < CHUNK * 8; i += THREADS) {
                int t = i >> 3, d8 = i & 7;
                uint32_t off = swz((uint32_t)(t * 128 + d8 * 16));
                float4 a = kc[t * 16 + d8 * 2];
                float4 b = kc[t * 16 + d8 * 2 + 1];
                float4 va = vc[t * 16 + d8 * 2];
                float4 vb = vc[t * 16 + d8 * 2 + 1];
                uint32_t h0,l0,h1,l1,h2,l2,h3,l3;
                splitpack_fast(a.x, a.y, h0, l0);
                splitpack_fast(a.z, a.w, h1, l1);
                splitpack_fast(b.x, b.y, h2, l2);
                splitpack_fast(b.z, b.w, h3, l3);
                *(uint4*)(smem + SM_KH + off) = make_uint4(h0, h1, h2, h3);
                *(uint4*)(smem + SM_KL + off) = make_uint4(l0, l1, l2, l3);
                *(uint4*)(smem + SM_VF + off) = make_uint4(packh2(va.x, va.y), packh2(va.z, va.w),
                                                           packh2(vb.x, vb.y), packh2(vb.z, vb.w));
            }
        }
        __syncthreads();           // tiles visible

        // ---- L2-prefetch next chunk (no registers, overlaps GEMMs) ----
        if (chunk < NCHUNK - 1) {
            const int nbase = base + CHUNK * D_DIM * 4;
            if (tid < 128) prefetch_l2(kg + nbase + tid * 128);
            else           prefetch_l2(vg + nbase + (tid - 128) * 128);
        }

        // ---- GEMM1: S = Q @ K^T  [16 x 64] per warp, split-3 bf16 ----
        float acc[8][4];
        #pragma unroll
        for (int nt = 0; nt < 8; ++nt)
            #pragma unroll
            for (int e = 0; e < 4; ++e) acc[nt][e] = 0.0f;

        #pragma unroll
        for (int k16 = 0; k16 < 4; ++k16) {
            uint32_t Ah[4], Al[4];
            {
                uint32_t off = swz((uint32_t)((s0 + a_row) * 128 + k16 * 32 + a_kh * 16));
                LDSM_X4(Ah[0], Ah[1], Ah[2], Ah[3], sb + SM_QH + off);
                LDSM_X4(Al[0], Al[1], Al[2], Al[3], sb + SM_QL + off);
            }
            #pragma unroll
            for (int ntp = 0; ntp < 4; ++ntp) {
                uint32_t Bh[2][2], Bl[2][2];
                uint32_t off = swz((uint32_t)((ntp * 16 + b_nh + b_row) * 128 + k16 * 32 + b_kh));
                LDSM_X4(Bh[0][0], Bh[0][1], Bh[1][0], Bh[1][1], sb + SM_KH + off);
                LDSM_X4(Bl[0][0], Bl[0][1], Bl[1][0], Bl[1][1], sb + SM_KL + off);
                #pragma unroll
                for (int j = 0; j < 2; ++j) {
                    int nt = 2 * ntp + j;
                    mma_bf16(acc[nt], Ah, Bh[j]);
                    mma_bf16(acc[nt], Ah, Bl[j]);
                    mma_bf16(acc[nt], Al, Bh[j]);
                }
            }
        }

        // ---- mask + online max ----
        #pragma unroll
        for (int nt = 0; nt < 8; ++nt)
            #pragma unroll
            for (int e = 0; e < 4; ++e) {
                float v = acc[nt][e];
                acc[nt][e] = (v == 0.0f) ? -100000.0f : v;
            }
        float cm1 = -3.0e38f, cm2 = -3.0e38f;
        #pragma unroll
        for (int nt = 0; nt < 8; ++nt) {
            cm1 = fmaxf(cm1, fmaxf(acc[nt][0], acc[nt][1]));
            cm2 = fmaxf(cm2, fmaxf(acc[nt][2], acc[nt][3]));
        }
        cm1 = fmaxf(cm1, __shfl_xor_sync(0xFFFFFFFFu, cm1, 1));
        cm1 = fmaxf(cm1, __shfl_xor_sync(0xFFFFFFFFu, cm1, 2));
        cm2 = fmaxf(cm2, __shfl_xor_sync(0xFFFFFFFFu, cm2, 1));
        cm2 = fmaxf(cm2, __shfl_xor_sync(0xFFFFFFFFu, cm2, 2));

        // conditional rescale: skip when no lane's row max changed
        bool nochg = (cm1 <= m1) & (cm2 <= m2);
        if (!__all_sync(0xFFFFFFFFu, nochg)) {
            float nm1 = fmaxf(m1, cm1), nm2 = fmaxf(m2, cm2);
            float sc1 = __expf(m1 - nm1), sc2 = __expf(m2 - nm2);
            m1 = nm1; m2 = nm2;
            c_rs[0] *= sc1; c_rs[1] *= sc1;
            c_rs[2] *= sc2; c_rs[3] *= sc2;
            #pragma unroll
            for (int nt = 0; nt < 8; ++nt) {
                Oacc[nt][0] *= sc1; Oacc[nt][1] *= sc1;
                Oacc[nt][2] *= sc2; Oacc[nt][3] *= sc2;
            }
        }

        // ---- exp directly into packed fp16 P fragments ----
        const float mlog1 = -m1 * L2E, mlog2 = -m2 * L2E;
        uint32_t Pf[4][4];
        #pragma unroll
        for (int nt = 0; nt < 8; ++nt) {
            int kc = nt >> 1, j = nt & 1;
            Pf[kc][2 * j]     = ex2h2(acc[nt][0], acc[nt][1], mlog1);
            Pf[kc][2 * j + 1] = ex2h2(acc[nt][2], acc[nt][3], mlog2);
        }
        // row sums: rs += P @ ones  (consistent with GEMM2's quantized P)
        #pragma unroll
        for (int kc = 0; kc < 4; ++kc) mma_f16(c_rs, Pf[kc], onesb);

        // ---- GEMM2: O += P @ V  [16 x 64] per warp, single fp16 ----
        #pragma unroll
        for (int k16 = 0; k16 < 4; ++k16) {
            #pragma unroll
            for (int ntp = 0; ntp < 4; ++ntp) {
                uint32_t Vf[2][2];
                uint32_t off = swz((uint32_t)((k16 * 16 + b_toff) * 128 + ntp * 32 + b_ch));
                LDSM_X4T(Vf[0][0], Vf[0][1], Vf[1][0], Vf[1][1], sb + SM_VF + off);
                mma_f16(Oacc[2 * ntp],     Pf[k16], Vf[0]);
                mma_f16(Oacc[2 * ntp + 1], Pf[k16], Vf[1]);
            }
        }
    }

    // ---- epilogue: normalize by ones-MMA row sums, store ----
    float inv1 = 1.0f / c_rs[0];
    float inv2 = 1.0f / c_rs[2];

    float* ob = out + (size_t)bw * (S_DIM * D_DIM);
    const int r1 = s0 + (l >> 2), r2 = r1 + 8;
    const int ec = (l & 3) * 2;
    #pragma unroll
    for (int nt = 0; nt < 8; ++nt) {
        int c = nt * 8 + ec;
        *(float2*)(ob + r1 * 64 + c) = make_float2(Oacc[nt][0] * inv1, Oacc[nt][1] * inv1);
        *(float2*)(ob + r2 * 64 + c) = make_float2(Oacc[nt][2] * inv2, Oacc[nt][3] * inv2);
    }
}

extern "C" void kernel_launch(void* const* d_in, const int* in_sizes, int n_in,
                              void* d_out, int out_size)
{
    const float* q    = (const float*)d_in[0];
    const float* keys = (const float*)d_in[1];
    const float* vals = (const float*)d_in[2];
    float* out = (float*)d_out;

    const int BW = in_sizes[1] / (T_DIM * D_DIM);   // 2048

    cudaFuncSetAttribute(attn_flash7_kernel,
                         cudaFuncAttributeMaxDynamicSharedMemorySize, SMEM_BYTES);
    attn_flash7_kernel<<<BW, THREADS, SMEM_BYTES>>>(q, keys, vals, out);
}